// round 16
// baseline (speedup 1.0000x reference)
#include <cuda_runtime.h>
#include <cstdint>

#define SEQ   2048
#define DH    128
#define BQ    256
#define BK    64
#define NBH   64
#define NKT   (SEQ / BK)     // 32
#define KP    136            // %32==8 -> conflict-free LDS.64
#define VP    72
#define PP    72
#define KBUF  (64 * KP)      // 8704 floats
#define VBUF  (128 * VP)     // 9216 floats
#define KS_OFF 0
#define VS_OFF (2 * KBUF)                   // 17408
#define PS_OFF (VS_OFF + 2 * VBUF)          // 35840
#define SMEM_FLOATS (PS_OFF + 8 * 32 * PP)  // 54272
#define SMEM_BYTES (SMEM_FLOATS * 4)        // 217088 B

__device__ float g_Qp[(size_t)NBH * SEQ * DH];   // tf32, pre-scaled, dim-pair-permuted
__device__ float g_Kp[(size_t)NBH * SEQ * DH];   // tf32, dim-pair-permuted
__device__ float g_Vt[(size_t)NBH * DH * SEQ];   // tf32, [dim][key], key-pair-permuted

__device__ __forceinline__ float tf32r(float x) {
    uint32_t u; asm("cvt.rna.tf32.f32 %0, %1;" : "=r"(u) : "f"(x));
    return __uint_as_float(u);
}
__device__ __forceinline__ uint32_t smem_u32(const void* p) {
    uint32_t a;
    asm("{ .reg .u64 t; cvta.to.shared.u64 t, %1; cvt.u32.u64 %0, t; }" : "=r"(a) : "l"(p));
    return a;
}
__device__ __forceinline__ void cp16(uint32_t dst, const void* src) {
    asm volatile("cp.async.cg.shared.global [%0], [%1], 16;" :: "r"(dst), "l"(src) : "memory");
}
#define CP_COMMIT() asm volatile("cp.async.commit_group;" ::: "memory")
#define CP_WAIT1()  asm volatile("cp.async.wait_group 1;" ::: "memory")

__device__ __forceinline__ void mma_tf32(float c[4],
                                         float a0, float a1, float a2, float a3,
                                         float b0, float b1) {
    asm volatile(
        "mma.sync.aligned.m16n8k8.row.col.f32.tf32.tf32.f32 "
        "{%0,%1,%2,%3}, {%4,%5,%6,%7}, {%8,%9}, {%0,%1,%2,%3};"
        : "+f"(c[0]), "+f"(c[1]), "+f"(c[2]), "+f"(c[3])
        : "r"(__float_as_uint(a0)), "r"(__float_as_uint(a1)),
          "r"(__float_as_uint(a2)), "r"(__float_as_uint(a3)),
          "r"(__float_as_uint(b0)), "r"(__float_as_uint(b1)));
}

// fused prep: q/k rounded+dim-permuted, v rounded+transposed+key-permuted
__global__ void prep_fused(const float* __restrict__ q, const float* __restrict__ k,
                           const float* __restrict__ v) {
    __shared__ float t[32][33];
    const float sc = 0.08838834764831845f;   // 1/sqrt(128)
    int k0 = blockIdx.x * 32, d0 = blockIdx.y * 32, bh = blockIdx.z;
    int tx = threadIdx.x, ty = threadIdx.y;
    size_t base = (size_t)bh * SEQ * DH;
    size_t src = base + (size_t)(k0 + ty) * DH + d0 + tx;

    int c = d0 + tx;
    int cperm = (c & ~7) + ((c & 3) * 2 + ((c & 7) >> 2));
    size_t dstqk = base + (size_t)(k0 + ty) * DH + cperm;
    g_Qp[dstqk] = tf32r(q[src] * sc);
    g_Kp[dstqk] = tf32r(k[src]);

    t[ty][tx] = tf32r(v[src]);
    __syncthreads();
    int kperm = (tx & ~7) + ((tx & 3) * 2 + ((tx & 7) >> 2));
    g_Vt[(size_t)bh * DH * SEQ + (size_t)(d0 + ty) * SEQ + k0 + kperm] = t[tx][ty];
}

__device__ __forceinline__ void load_K(uint32_t sb, int tid, size_t base, int kt, int buf) {
    const float* kg = g_Kp + base + (size_t)kt * BK * DH;
#pragma unroll
    for (int it = 0; it < 8; it++) {
        int idx = tid + it * 256;        // 64 rows x 32 float4
        int n = idx >> 5, c = idx & 31;
        cp16(sb + (uint32_t)(KS_OFF + buf * KBUF + n * KP + 4 * c) * 4u,
             kg + (size_t)n * DH + 4 * c);
    }
}
__device__ __forceinline__ void load_V(uint32_t sb, int tid, int bh, int kt, int buf) {
    const float* vg = g_Vt + (size_t)bh * DH * SEQ + kt * BK;
#pragma unroll
    for (int it = 0; it < 8; it++) {
        int idx = tid + it * 256;        // 128 dim-rows x 16 float4
        int n = idx >> 4, c = idx & 15;
        cp16(sb + (uint32_t)(VS_OFF + buf * VBUF + n * VP + 4 * c) * 4u,
             vg + (size_t)n * SEQ + 4 * c);
    }
}

__global__ void __launch_bounds__(256, 1)
fa_tf32_kernel(const float* __restrict__ mask, float* __restrict__ out) {
    extern __shared__ float smem[];
    const uint32_t sb = smem_u32(smem);

    const int tid  = threadIdx.x;
    const int w    = tid >> 5;
    const int lane = tid & 31;
    const int g    = lane >> 2;
    const int tg   = lane & 3;

    float* Ps = smem + PS_OFF + w * (32 * PP);

    const int qt = blockIdx.x;
    const int bh = blockIdx.y;
    const int q0 = qt * BQ;
    const size_t base = (size_t)bh * SEQ * DH;

    const int pp0 = ((2 * tg) & 3) * 2 + ((2 * tg) >> 2);
    const int pp1 = ((2 * tg + 1) & 3) * 2 + ((2 * tg + 1) >> 2);

    // warp owns 32 q-rows: block0 rows g,g+8 ; block1 rows g+16,g+24
    const float* qb = g_Qp + base + (size_t)(q0 + w * 32) * DH;

    const float* mrow0 = mask + (size_t)(q0 + w * 32 + g)      * SEQ;
    const float* mrow1 = mask + (size_t)(q0 + w * 32 + g + 8)  * SEQ;
    const float* mrow2 = mask + (size_t)(q0 + w * 32 + g + 16) * SEQ;
    const float* mrow3 = mask + (size_t)(q0 + w * 32 + g + 24) * SEQ;

    float oacc0[16][4], oacc1[16][4];
#pragma unroll
    for (int d = 0; d < 16; d++) {
        oacc0[d][0] = 0.f; oacc0[d][1] = 0.f; oacc0[d][2] = 0.f; oacc0[d][3] = 0.f;
        oacc1[d][0] = 0.f; oacc1[d][1] = 0.f; oacc1[d][2] = 0.f; oacc1[d][3] = 0.f;
    }
    float l00 = 0.f, l01 = 0.f, l10 = 0.f, l11 = 0.f;

    load_K(sb, tid, base, 0, 0);
    load_V(sb, tid, bh, 0, 0);
    CP_COMMIT();

    for (int kt = 0; kt < NKT; kt++) {
        const int cur = kt & 1, nxt = cur ^ 1;
        __syncthreads();
        if (kt + 1 < NKT) { load_K(sb, tid, base, kt + 1, nxt); load_V(sb, tid, bh, kt + 1, nxt); }
        CP_COMMIT();
        CP_WAIT1();
        __syncthreads();

        const float* Ks = smem + KS_OFF + cur * KBUF;
        const float* Vs = smem + VS_OFF + cur * VBUF;

        // ---- S = Q K^T, 2 row-blocks share every K B-fragment; Q streamed per k-step ----
        float sacc0[8][4], sacc1[8][4];
#pragma unroll
        for (int nb = 0; nb < 8; nb++) {
            sacc0[nb][0] = 0.f; sacc0[nb][1] = 0.f; sacc0[nb][2] = 0.f; sacc0[nb][3] = 0.f;
            sacc1[nb][0] = 0.f; sacc1[nb][1] = 0.f; sacc1[nb][2] = 0.f; sacc1[nb][3] = 0.f;
        }
#pragma unroll
        for (int s = 0; s < 16; s++) {
            const int qo = 8 * s + 2 * tg;
            float2 A0 = *(const float2*)(qb + (size_t)g        * DH + qo);
            float2 A1 = *(const float2*)(qb + (size_t)(g + 8)  * DH + qo);
            float2 B0 = *(const float2*)(qb + (size_t)(g + 16) * DH + qo);
            float2 B1 = *(const float2*)(qb + (size_t)(g + 24) * DH + qo);
#pragma unroll
            for (int nb = 0; nb < 8; nb++) {
                float2 kb2 = *(const float2*)(Ks + (8 * nb + g) * KP + qo);
                mma_tf32(sacc0[nb], A0.x, A1.x, A0.y, A1.y, kb2.x, kb2.y);
                mma_tf32(sacc1[nb], B0.x, B1.x, B0.y, B1.y, kb2.x, kb2.y);
            }
        }

        // ---- mask + exp, P -> smem (mask loaded per-nb; small live set) ----
#pragma unroll
        for (int nb = 0; nb < 8; nb++) {
            const int mo = kt * BK + 8 * nb + 2 * tg;
            float2 m0 = *(const float2*)(mrow0 + mo);
            float2 m1 = *(const float2*)(mrow1 + mo);
            float2 m2 = *(const float2*)(mrow2 + mo);
            float2 m3 = *(const float2*)(mrow3 + mo);
            float p00 = __expf(sacc0[nb][0] + m0.x);
            float p01 = __expf(sacc0[nb][1] + m0.y);
            float p02 = __expf(sacc0[nb][2] + m1.x);
            float p03 = __expf(sacc0[nb][3] + m1.y);
            float p10 = __expf(sacc1[nb][0] + m2.x);
            float p11 = __expf(sacc1[nb][1] + m2.y);
            float p12 = __expf(sacc1[nb][2] + m3.x);
            float p13 = __expf(sacc1[nb][3] + m3.y);
            l00 += p00 + p01;  l01 += p02 + p03;
            l10 += p10 + p11;  l11 += p12 + p13;
            Ps[g        * PP + 8 * nb + pp0] = tf32r(p00);
            Ps[g        * PP + 8 * nb + pp1] = tf32r(p01);
            Ps[(g + 8)  * PP + 8 * nb + pp0] = tf32r(p02);
            Ps[(g + 8)  * PP + 8 * nb + pp1] = tf32r(p03);
            Ps[(g + 16) * PP + 8 * nb + pp0] = tf32r(p10);
            Ps[(g + 16) * PP + 8 * nb + pp1] = tf32r(p11);
            Ps[(g + 24) * PP + 8 * nb + pp0] = tf32r(p12);
            Ps[(g + 24) * PP + 8 * nb + pp1] = tf32r(p13);
        }
        __syncwarp();

        // ---- O += P V, 2 row-blocks share every V B-fragment ----
#pragma unroll
        for (int kb = 0; kb < 8; kb++) {
            const int po = 8 * kb + 2 * tg;
            float2 pa0 = *(const float2*)(Ps + g        * PP + po);
            float2 pa1 = *(const float2*)(Ps + (g + 8)  * PP + po);
            float2 pb0 = *(const float2*)(Ps + (g + 16) * PP + po);
            float2 pb1 = *(const float2*)(Ps + (g + 24) * PP + po);
#pragma unroll
            for (int db = 0; db < 16; db++) {
                float2 vb = *(const float2*)(Vs + (8 * db + g) * VP + po);
                mma_tf32(oacc0[db], pa0.x, pa1.x, pa0.y, pa1.y, vb.x, vb.y);
                mma_tf32(oacc1[db], pb0.x, pb1.x, pb0.y, pb1.y, vb.x, vb.y);
            }
        }
    }

    // ---- epilogue ----
    l00 += __shfl_xor_sync(0xffffffffu, l00, 1);
    l00 += __shfl_xor_sync(0xffffffffu, l00, 2);
    l01 += __shfl_xor_sync(0xffffffffu, l01, 1);
    l01 += __shfl_xor_sync(0xffffffffu, l01, 2);
    l10 += __shfl_xor_sync(0xffffffffu, l10, 1);
    l10 += __shfl_xor_sync(0xffffffffu, l10, 2);
    l11 += __shfl_xor_sync(0xffffffffu, l11, 1);
    l11 += __shfl_xor_sync(0xffffffffu, l11, 2);
    float i00 = 1.0f / l00, i01 = 1.0f / l01, i10 = 1.0f / l10, i11 = 1.0f / l11;

    float* op = out + base + (size_t)(q0 + w * 32) * DH;
#pragma unroll
    for (int db = 0; db < 16; db++) {
        int c = 8 * db + 2 * tg;
        *(float2*)(op + (size_t)g        * DH + c) = make_float2(oacc0[db][0] * i00, oacc0[db][1] * i00);
        *(float2*)(op + (size_t)(g + 8)  * DH + c) = make_float2(oacc0[db][2] * i01, oacc0[db][3] * i01);
        *(float2*)(op + (size_t)(g + 16) * DH + c) = make_float2(oacc1[db][0] * i10, oacc1[db][1] * i10);
        *(float2*)(op + (size_t)(g + 24) * DH + c) = make_float2(oacc1[db][2] * i11, oacc1[db][3] * i11);
    }
}

extern "C" void kernel_launch(void* const* d_in, const int* in_sizes, int n_in,
                              void* d_out, int out_size) {
    const float* q    = (const float*)d_in[0];
    const float* k    = (const float*)d_in[1];
    const float* v    = (const float*)d_in[2];
    const float* mask = (const float*)d_in[3];
    float* out = (float*)d_out;

    prep_fused<<<dim3(SEQ / 32, DH / 32, NBH), dim3(32, 32)>>>(q, k, v);

    cudaFuncSetAttribute(fa_tf32_kernel,
                         cudaFuncAttributeMaxDynamicSharedMemorySize, SMEM_BYTES);
    cudaFuncSetAttribute(fa_tf32_kernel,
                         cudaFuncAttributePreferredSharedMemoryCarveout, 100);

    dim3 grid(SEQ / BQ, NBH);   // (8, 64)
    fa_tf32_kernel<<<grid, 256, SMEM_BYTES>>>(mask, out);
}